// round 7
// baseline (speedup 1.0000x reference)
#include <cuda_runtime.h>

// softmax(f[n]+g[m]) over m cancels f[n] -> all output rows identical.
// K1: 64 CTAs reduce x with exp(g) weights -> partials transposed [17][64]
// K2 (PDL): preloads Wk + sets up addresses BEFORE cudaGridDependencySynchronize(),
//           then reduces partials, computes the 128-float row, broadcasts 4MB.

#define D_IN 16
#define DH   18
#define K1_BLOCKS 64
#define K1_THREADS 128            // 64*128 = 8192 rows, 1 row/thread
#define K2_BLOCKS 128
#define K2_THREADS 544            // 17 warps
#define ROWS_PER_B2 (8192 / K2_BLOCKS)   // 64

__device__ float g_part[17 * K1_BLOCKS];   // [col][block]

__global__ void __launch_bounds__(K1_THREADS, 1) k1_reduce(
    const float* __restrict__ x,
    const float* __restrict__ W,
    const float* __restrict__ a)
{
    __shared__ float wa2[16];
    __shared__ float wsum[4][18];   // 4 warps x 17 (+pad)
    int tid  = threadIdx.x;
    int warp = tid >> 5, lane = tid & 31;

    // issue x loads FIRST (independent of wa2) so they fly during the sync
    int m = blockIdx.x * K1_THREADS + tid;
    const float4* xr = reinterpret_cast<const float4*>(x + (size_t)m * D_IN);
    float4 x0 = xr[0], x1 = xr[1], x2 = xr[2], x3 = xr[3];

    if (tid < 16) {
        float s = 0.f;
        #pragma unroll
        for (int j = 0; j < DH; ++j) s += W[tid * DH + j] * a[DH + j];
        wa2[tid] = s;
    }
    __syncthreads();

    float xv[16] = { x0.x, x0.y, x0.z, x0.w,  x1.x, x1.y, x1.z, x1.w,
                     x2.x, x2.y, x2.z, x2.w,  x3.x, x3.y, x3.z, x3.w };
    float g = 0.f;
    #pragma unroll
    for (int k = 0; k < 16; ++k) g += xv[k] * wa2[k];
    float e = expf(g);              // |g| <~ 3: no max-shift needed

    float p[17];
    #pragma unroll
    for (int k = 0; k < 16; ++k) p[k] = e * xv[k];
    p[16] = e;

    #pragma unroll
    for (int off = 16; off > 0; off >>= 1) {
        #pragma unroll
        for (int i = 0; i < 17; ++i)
            p[i] += __shfl_down_sync(0xffffffffu, p[i], off);
    }
    if (lane == 0) {
        #pragma unroll
        for (int i = 0; i < 17; ++i) wsum[warp][i] = p[i];
    }
    __syncthreads();

    if (tid < 17) {
        float s = wsum[0][tid] + wsum[1][tid] + wsum[2][tid] + wsum[3][tid];
        g_part[tid * K1_BLOCKS + blockIdx.x] = s;   // transposed for K2
    }
}

__global__ void __launch_bounds__(K2_THREADS, 1) k2_finish(
    const float* __restrict__ Wk,
    float* __restrict__ out)
{
    __shared__ float red[17];
    __shared__ float orow[128];
    int tid  = threadIdx.x;
    int warp = tid >> 5, lane = tid & 31;

    // ---- pre-sync phase: everything independent of K1 ----
    // preload Wk column for this (h,d) thread
    float wcol[16];
    if (tid < 128) {
        int h = tid >> 4, d = tid & 15;
        const float* Wh = Wk + h * (D_IN * D_IN);
        #pragma unroll
        for (int k = 0; k < 16; ++k) wcol[k] = Wh[k * 16 + d];
    }
    float4* o4 = reinterpret_cast<float4*>(out);
    int c4 = tid & 31;
    int r0 = tid >> 5;
    int rowbase = blockIdx.x * ROWS_PER_B2;

#if __CUDA_ARCH__ >= 900
    cudaGridDependencySynchronize();   // wait for K1's results (PDL)
#endif

    // warp w reduces column w: 64 contiguous floats, 2 per lane
    if (warp < 17) {
        float v = g_part[warp * K1_BLOCKS + lane]
                + g_part[warp * K1_BLOCKS + 32 + lane];
        #pragma unroll
        for (int off = 16; off > 0; off >>= 1)
            v += __shfl_down_sync(0xffffffffu, v, off);
        if (lane == 0) red[warp] = v;
    }
    __syncthreads();

    if (tid < 128) {
        float invZ = 1.0f / red[16];
        float s = 0.f;
        #pragma unroll
        for (int k = 0; k < 16; ++k) s += red[k] * wcol[k];
        orow[tid] = s * invZ;
    }
    __syncthreads();

    // broadcast: 64 rows/CTA = 2048 float4, 512 threads x 4 stores
    if (tid < 512) {
        float4 val = make_float4(orow[c4 * 4 + 0], orow[c4 * 4 + 1],
                                 orow[c4 * 4 + 2], orow[c4 * 4 + 3]);
        #pragma unroll
        for (int i = 0; i < 4; ++i) {
            int r = rowbase + r0 + i * 16;
            o4[(size_t)r * 32 + c4] = val;
        }
    }
}

extern "C" void kernel_launch(void* const* d_in, const int* in_sizes, int n_in,
                              void* d_out, int out_size) {
    const float* x  = (const float*)d_in[0];  // (8192,16)
    const float* W  = (const float*)d_in[1];  // (16,18)
    const float* a  = (const float*)d_in[2];  // (36,1)
    const float* Wk = (const float*)d_in[3];  // (8,16,16)
    float* out = (float*)d_out;               // (8192,128)

    k1_reduce<<<K1_BLOCKS, K1_THREADS>>>(x, W, a);

    // K2 with programmatic dependent launch: overlaps launch + prologue with K1
    cudaLaunchAttribute attrs[1];
    attrs[0].id = cudaLaunchAttributeProgrammaticStreamSerialization;
    attrs[0].val.programmaticStreamSerializationAllowed = 1;
    cudaLaunchConfig_t cfg = {};
    cfg.gridDim  = dim3(K2_BLOCKS, 1, 1);
    cfg.blockDim = dim3(K2_THREADS, 1, 1);
    cfg.dynamicSmemBytes = 0;
    cfg.stream = 0;
    cfg.attrs = attrs;
    cfg.numAttrs = 1;
    cudaLaunchKernelEx(&cfg, k2_finish, Wk, (float*)d_out);
}

// round 8
// speedup vs baseline: 1.0332x; 1.0332x over previous
#include <cuda_runtime.h>

// softmax(f[n]+g[m]) over m cancels f[n] -> all output rows identical.
// K1: 64 CTAs reduce x with exp(g) weights -> partials transposed [17][64]
// K2 (PDL): preloads Wk + sets up addresses BEFORE cudaGridDependencySynchronize(),
//           then reduces partials, computes the 128-float row, broadcasts 4MB.

#define D_IN 16
#define DH   18
#define K1_BLOCKS 64
#define K1_THREADS 128            // 64*128 = 8192 rows, 1 row/thread
#define K2_BLOCKS 128
#define K2_THREADS 544            // 17 warps
#define ROWS_PER_B2 (8192 / K2_BLOCKS)   // 64

__device__ float g_part[17 * K1_BLOCKS];   // [col][block]

__global__ void __launch_bounds__(K1_THREADS, 1) k1_reduce(
    const float* __restrict__ x,
    const float* __restrict__ W,
    const float* __restrict__ a)
{
    __shared__ float wa2[16];
    __shared__ float wsum[4][18];   // 4 warps x 17 (+pad)
    int tid  = threadIdx.x;
    int warp = tid >> 5, lane = tid & 31;

    // issue x loads FIRST (independent of wa2) so they fly during the sync
    int m = blockIdx.x * K1_THREADS + tid;
    const float4* xr = reinterpret_cast<const float4*>(x + (size_t)m * D_IN);
    float4 x0 = xr[0], x1 = xr[1], x2 = xr[2], x3 = xr[3];

    if (tid < 16) {
        float s = 0.f;
        #pragma unroll
        for (int j = 0; j < DH; ++j) s += W[tid * DH + j] * a[DH + j];
        wa2[tid] = s;
    }
    __syncthreads();

    float xv[16] = { x0.x, x0.y, x0.z, x0.w,  x1.x, x1.y, x1.z, x1.w,
                     x2.x, x2.y, x2.z, x2.w,  x3.x, x3.y, x3.z, x3.w };
    float g = 0.f;
    #pragma unroll
    for (int k = 0; k < 16; ++k) g += xv[k] * wa2[k];
    float e = expf(g);              // |g| <~ 3: no max-shift needed

    float p[17];
    #pragma unroll
    for (int k = 0; k < 16; ++k) p[k] = e * xv[k];
    p[16] = e;

    #pragma unroll
    for (int off = 16; off > 0; off >>= 1) {
        #pragma unroll
        for (int i = 0; i < 17; ++i)
            p[i] += __shfl_down_sync(0xffffffffu, p[i], off);
    }
    if (lane == 0) {
        #pragma unroll
        for (int i = 0; i < 17; ++i) wsum[warp][i] = p[i];
    }
    __syncthreads();

    if (tid < 17) {
        float s = wsum[0][tid] + wsum[1][tid] + wsum[2][tid] + wsum[3][tid];
        g_part[tid * K1_BLOCKS + blockIdx.x] = s;   // transposed for K2
    }
}

__global__ void __launch_bounds__(K2_THREADS, 1) k2_finish(
    const float* __restrict__ Wk,
    float* __restrict__ out)
{
    __shared__ float red[17];
    __shared__ float orow[128];
    int tid  = threadIdx.x;
    int warp = tid >> 5, lane = tid & 31;

    // ---- pre-sync phase: everything independent of K1 ----
    // preload Wk column for this (h,d) thread
    float wcol[16];
    if (tid < 128) {
        int h = tid >> 4, d = tid & 15;
        const float* Wh = Wk + h * (D_IN * D_IN);
        #pragma unroll
        for (int k = 0; k < 16; ++k) wcol[k] = Wh[k * 16 + d];
    }
    float4* o4 = reinterpret_cast<float4*>(out);
    int c4 = tid & 31;
    int r0 = tid >> 5;
    int rowbase = blockIdx.x * ROWS_PER_B2;

#if __CUDA_ARCH__ >= 900
    cudaGridDependencySynchronize();   // wait for K1's results (PDL)
#endif

    // warp w reduces column w: 64 contiguous floats, 2 per lane
    if (warp < 17) {
        float v = g_part[warp * K1_BLOCKS + lane]
                + g_part[warp * K1_BLOCKS + 32 + lane];
        #pragma unroll
        for (int off = 16; off > 0; off >>= 1)
            v += __shfl_down_sync(0xffffffffu, v, off);
        if (lane == 0) red[warp] = v;
    }
    __syncthreads();

    if (tid < 128) {
        float invZ = 1.0f / red[16];
        float s = 0.f;
        #pragma unroll
        for (int k = 0; k < 16; ++k) s += red[k] * wcol[k];
        orow[tid] = s * invZ;
    }
    __syncthreads();

    // broadcast: 64 rows/CTA = 2048 float4, 512 threads x 4 stores
    if (tid < 512) {
        float4 val = make_float4(orow[c4 * 4 + 0], orow[c4 * 4 + 1],
                                 orow[c4 * 4 + 2], orow[c4 * 4 + 3]);
        #pragma unroll
        for (int i = 0; i < 4; ++i) {
            int r = rowbase + r0 + i * 16;
            o4[(size_t)r * 32 + c4] = val;
        }
    }
}

extern "C" void kernel_launch(void* const* d_in, const int* in_sizes, int n_in,
                              void* d_out, int out_size) {
    const float* x  = (const float*)d_in[0];  // (8192,16)
    const float* W  = (const float*)d_in[1];  // (16,18)
    const float* a  = (const float*)d_in[2];  // (36,1)
    const float* Wk = (const float*)d_in[3];  // (8,16,16)
    float* out = (float*)d_out;               // (8192,128)

    k1_reduce<<<K1_BLOCKS, K1_THREADS>>>(x, W, a);

    // K2 with programmatic dependent launch: overlaps launch + prologue with K1
    cudaLaunchAttribute attrs[1];
    attrs[0].id = cudaLaunchAttributeProgrammaticStreamSerialization;
    attrs[0].val.programmaticStreamSerializationAllowed = 1;
    cudaLaunchConfig_t cfg = {};
    cfg.gridDim  = dim3(K2_BLOCKS, 1, 1);
    cfg.blockDim = dim3(K2_THREADS, 1, 1);
    cfg.dynamicSmemBytes = 0;
    cfg.stream = 0;
    cfg.attrs = attrs;
    cfg.numAttrs = 1;
    cudaLaunchKernelEx(&cfg, k2_finish, Wk, (float*)d_out);
}